// round 15
// baseline (speedup 1.0000x reference)
#include <cuda_runtime.h>
#include <cuda_bf16.h>

// ---------------------------------------------------------------------------
// AliasFreeActivation: bias -> up2x(12x12 FIR, pad10, gain4) -> lrelu*sqrt2,
// clamp(+-256) -> 12x12 FIR down2x.
// Input [8,128,128,128] f32 -> mid [264,264] -> out [8,128,127,127] f32.
//
// Block = 32x64 output tile, 256 threads, 3 CTAs/SM (cross-CTA overlap hides
// barrier tails). Filters in __constant__ (uniform port). Input stored twice
// (sA, sB=shift-1) so overlapping pairs are direct LDS.64. Phase B computes
// an (even,odd) mid-row PAIR per job (7 shared input rows loaded once). Mid
// parity-split into even/odd half-arrays (conflict-free stride-73). Phase C:
// 4 row groups x 8 rows, compile-time trip counts. All FMAs are fma.rn.f32x2.
// ---------------------------------------------------------------------------

#define H      128
#define W      128
#define OHW    127
#define TY     32
#define TX     64
#define MSTR2  73          // half-mid row stride in (E,O) u64 pairs (9 mod 16)
#define INH    43
#define INW    78          // even => 8B-aligned u64 rows; u64 stride 39%16==7
#define NTHREADS 256

#define S_SA_OFF    0
#define S_SB_OFF    (INH*INW)                   // 3354
#define S_MIDE_OFF  (2*INH*INW)                 // 6708  (byte 26832, 16B)
#define S_MIDO_OFF  (S_MIDE_OFF + 37*MSTR2*2)   // 6708+5402 = 12110
#define SMEM_FLOATS (S_MIDO_OFF + 37*MSTR2*2)   // 17512 -> 70048 B

typedef unsigned long long u64;

__constant__ __align__(16) float c_fu[144];
__constant__ __align__(16) float c_fd[144];

__device__ __forceinline__ u64 ffma2(u64 a, u64 b, u64 c) {
    u64 d;
    asm("fma.rn.f32x2 %0, %1, %2, %3;" : "=l"(d) : "l"(a), "l"(b), "l"(c));
    return d;
}
__device__ __forceinline__ float2 unpack2(u64 d) {
    float2 f;
    asm("mov.b64 {%0, %1}, %2;" : "=f"(f.x), "=f"(f.y) : "l"(d));
    return f;
}

// Phase C worker: NR output rows, NM = 2*NR+10 mid rows. Compile-time trip
// counts -> full unroll, static rlo/rhi/ky folding, pipelinable loads.
template <int NR, int NM>
__device__ __forceinline__ void phase_c_group(const u64* __restrict__ hb,
                                              const u64* __restrict__ ob,
                                              u64* __restrict__ acc)
{
    #pragma unroll
    for (int r = 0; r < NR; r++) acc[r] = 0ull;

    #pragma unroll
    for (int mm = 0; mm < NM; mm++) {
        const u64* mrow = ((mm & 1) ? ob : hb) + (mm >> 1) * MSTR2;
        u64 md[6];
        #pragma unroll
        for (int s = 0; s < 6; s++) md[s] = mrow[s];

        const int rlo = (mm >= 12) ? ((mm - 10) >> 1) : 0;
        const int rhi = (mm >> 1) < (NR - 1) ? (mm >> 1) : (NR - 1);
        #pragma unroll
        for (int r = 0; r < NR; r++) {
            if (r < rlo || r > rhi) continue;       // folds at compile time
            const int ky = mm - 2 * r;              // compile-time constant
            const ulonglong2* fq = (const ulonglong2*)(c_fd + ky * 12);
            ulonglong2 f01 = fq[0], f23 = fq[1], f45 = fq[2];
            acc[r] = ffma2(md[0], f01.x, acc[r]);
            acc[r] = ffma2(md[1], f01.y, acc[r]);
            acc[r] = ffma2(md[2], f23.x, acc[r]);
            acc[r] = ffma2(md[3], f23.y, acc[r]);
            acc[r] = ffma2(md[4], f45.x, acc[r]);
            acc[r] = ffma2(md[5], f45.y, acc[r]);
        }
    }
}

__global__ __launch_bounds__(NTHREADS, 3)
void afa_fused_kernel(const float* __restrict__ in,
                      const float* __restrict__ bias,
                      float* __restrict__ out)
{
    extern __shared__ float sm[];
    float* s_sa   = sm + S_SA_OFF;
    float* s_sb   = sm + S_SB_OFF;
    u64*   s_midE = (u64*)(sm + S_MIDE_OFF);   // even mid rows, (E,O) pairs
    u64*   s_midO = (u64*)(sm + S_MIDO_OFF);   // odd  mid rows

    const int tid   = threadIdx.x;
    const int b     = blockIdx.x;
    const int plane = b >> 3;
    const int t8    = b & 7;
    const int oy0   = (t8 >> 1) * TY;
    const int ox0   = (t8 & 1) * TX;
    const int iy0   = oy0 - 5;
    const int ix0   = ox0 - 5;

    const float bv = __ldg(&bias[plane & 127]);
    const float* __restrict__ inp = in + (size_t)plane * (H * W);

    // ---- Phase A: dual input copies (+bias, zero pad OOB) ------------------
    for (int i = tid; i < INH * INW; i += NTHREADS) {
        const int r  = i / INW;
        const int cc = i - r * INW;
        const int gy = iy0 + r;
        const int gx = ix0 + cc;
        float v = 0.0f;
        if ((unsigned)gy < (unsigned)H && (unsigned)gx < (unsigned)W)
            v = __ldg(&inp[gy * W + gx]) + bv;
        s_sa[i] = v;                       // sA[w] = x[w]
        if (cc > 0) s_sb[i - 1] = v;       // sB[w] = x[w+1]
    }
    __syncthreads();

    // ---- Phase B: row-PAIR polyphase up-conv + activation ------------------
    // Job j<333: mid rows (2q, 2q+1), 16 columns (8 E/O pairs).
    // Shared input rows q..q+6 loaded once; even row uses fu row 2t (t<6),
    // odd row uses fu row 2t-1 (t>=1). Filter offsets are compile-time.
    // Gain 4 folded into activation gain G.
    const float G = 5.65685424949238019f;   // 4*sqrt(2)
    for (int j = tid; j < 333; j += NTHREADS) {
        const int chunk = j / 37;             // 0..8
        const int q     = j - chunk * 37;     // 0..36
        const int j0    = chunk * 8;          // pair/word column base (even)

        u64 ae[8], ao[8];
        #pragma unroll
        for (int jj = 0; jj < 8; jj++) { ae[jj] = 0ull; ao[jj] = 0ull; }

        #pragma unroll
        for (int t = 0; t < 7; t++) {
            const int rowoff = (q + t) * INW + j0;         // even offset
            const u64* pa = (const u64*)(s_sa + rowoff);   // (x[a],x[a+1]), a even
            const u64* pb = (const u64*)(s_sb + rowoff);   // (x[a],x[a+1]), a odd
            u64 pe[7], po[6];
            #pragma unroll
            for (int m = 0; m < 7; m++) pe[m] = pa[m];
            #pragma unroll
            for (int m = 0; m < 6; m++) po[m] = pb[m];

            #define PR(a) (((a) & 1) ? po[(a) >> 1] : pe[(a) >> 1])
            if (t < 6) {   // even mid row, filter row 2t (compile-time)
                const ulonglong2* fq = (const ulonglong2*)(c_fu + (2 * t) * 12);
                ulonglong2 f01 = fq[0], f23 = fq[1], f45 = fq[2];
                #pragma unroll
                for (int jj = 0; jj < 8; jj++) {
                    ae[jj] = ffma2(PR(jj + 0), f01.x, ae[jj]);
                    ae[jj] = ffma2(PR(jj + 1), f01.y, ae[jj]);
                    ae[jj] = ffma2(PR(jj + 2), f23.x, ae[jj]);
                    ae[jj] = ffma2(PR(jj + 3), f23.y, ae[jj]);
                    ae[jj] = ffma2(PR(jj + 4), f45.x, ae[jj]);
                    ae[jj] = ffma2(PR(jj + 5), f45.y, ae[jj]);
                }
            }
            if (t >= 1) {  // odd mid row, filter row 2t-1 (compile-time)
                const ulonglong2* fq = (const ulonglong2*)(c_fu + (2 * t - 1) * 12);
                ulonglong2 f01 = fq[0], f23 = fq[1], f45 = fq[2];
                #pragma unroll
                for (int jj = 0; jj < 8; jj++) {
                    ao[jj] = ffma2(PR(jj + 0), f01.x, ao[jj]);
                    ao[jj] = ffma2(PR(jj + 1), f01.y, ao[jj]);
                    ao[jj] = ffma2(PR(jj + 2), f23.x, ao[jj]);
                    ao[jj] = ffma2(PR(jj + 3), f23.y, ao[jj]);
                    ao[jj] = ffma2(PR(jj + 4), f45.x, ao[jj]);
                    ao[jj] = ffma2(PR(jj + 5), f45.y, ao[jj]);
                }
            }
            #undef PR
        }
        // activation (gain folded) + store pairs; stride 73 u64 (9 mod 16)
        u64* re = s_midE + q * MSTR2 + j0;
        u64* ro = s_midO + q * MSTR2 + j0;
        #pragma unroll
        for (int jj = 0; jj < 8; jj++) {
            float2 v = unpack2(ae[jj]);
            v.x = fminf(fmaxf(fmaxf(v.x, 0.2f * v.x) * G, -256.0f), 256.0f);
            v.y = fminf(fmaxf(fmaxf(v.y, 0.2f * v.y) * G, -256.0f), 256.0f);
            ((float2*)re)[jj] = v;
            float2 w = unpack2(ao[jj]);
            w.x = fminf(fmaxf(fmaxf(w.x, 0.2f * w.x) * G, -256.0f), 256.0f);
            w.y = fminf(fmaxf(fmaxf(w.y, 0.2f * w.y) * G, -256.0f), 256.0f);
            ((float2*)ro)[jj] = w;
        }
    }
    __syncthreads();

    // ---- Phase C: 12x12 down-conv stride 2, packed over (E,O) --------------
    // 8 warps = 4 row groups (8 rows each) x 2 col halves. lane = column.
    // Compile-time trip counts (no dynamic breaks).
    {
        const int wrp  = tid >> 5;
        const int lane = tid & 31;
        const int rg   = wrp >> 1;                  // 0..3
        const int c    = ((wrp & 1) << 5) + lane;   // 0..63
        const int r0   = 8 * rg;
        const u64* hb  = s_midE + r0 * MSTR2 + c;
        const u64* ob  = s_midO + r0 * MSTR2 + c;

        u64 acc[8];
        phase_c_group<8, 26>(hb, ob, acc);

        const int gx = ox0 + c;
        if (gx < OHW) {
            float* op = out + (size_t)plane * (OHW * OHW) + gx;
            #pragma unroll
            for (int r = 0; r < 8; r++) {
                const int gy = oy0 + r0 + r;
                if (gy < OHW) {
                    float2 v = unpack2(acc[r]);
                    op[gy * OHW] = v.x + v.y;
                }
            }
        }
    }
}

extern "C" void kernel_launch(void* const* d_in, const int* in_sizes, int n_in,
                              void* d_out, int out_size)
{
    const float* in   = (const float*)d_in[0];
    const float* bias = (const float*)d_in[1];
    const float* fu   = (const float*)d_in[2];
    const float* fd   = (const float*)d_in[3];
    float* out        = (float*)d_out;

    // Filters into constant memory (async D2D copies: graph-capturable).
    cudaMemcpyToSymbolAsync(c_fu, fu, 144 * sizeof(float), 0,
                            cudaMemcpyDeviceToDevice, 0);
    cudaMemcpyToSymbolAsync(c_fd, fd, 144 * sizeof(float), 0,
                            cudaMemcpyDeviceToDevice, 0);

    const size_t smem = SMEM_FLOATS * sizeof(float);   // 70048 B
    cudaFuncSetAttribute(afa_fused_kernel,
                         cudaFuncAttributeMaxDynamicSharedMemorySize, (int)smem);

    const int nblocks = 1024 * 8;
    afa_fused_kernel<<<nblocks, NTHREADS, smem>>>(in, bias, out);
}

// round 16
// speedup vs baseline: 1.3073x; 1.3073x over previous
#include <cuda_runtime.h>
#include <cuda_bf16.h>

// ---------------------------------------------------------------------------
// AliasFreeActivation: bias -> up2x(12x12 FIR, pad10, gain4) -> lrelu*sqrt2,
// clamp(+-256) -> 12x12 FIR down2x.
// Input [8,128,128,128] f32 -> mid [264,264] -> out [8,128,127,127] f32.
//
// Block = 32x64 output tile, 384 threads, 2 CTAs/SM. Filters in __constant__.
// Input stored twice (sA, sB=shift-1) -> phase-B pairs are direct LDS.64.
// Phase B: (even,odd) mid-row PAIR per job, 7 shared input rows loaded once;
// STS.128 stores (MSTR2=74, quad stride 37, conflict-free). Mid parity-split.
// Phase C: thread = 2 adjacent output columns; per mid row 4 LDS.128 load
// pairs 2lane..2lane+7 shared by both columns (-66% load instrs). Row groups
// 8x3 + 4x2 rows, compile-time trip counts. All FMAs are fma.rn.f32x2.
// ---------------------------------------------------------------------------

#define H      128
#define W      128
#define OHW    127
#define TY     32
#define TX     64
#define MSTR2  74          // half-mid row stride in u64 pairs (even -> 16B rows)
#define INH    43
#define INW    78          // even => 8B-aligned u64 rows; u64 stride 39%16==7
#define NTHREADS 384

#define S_SA_OFF    0
#define S_SB_OFF    (INH*INW)                   // 3354
#define S_MIDE_OFF  (2*INH*INW)                 // 6708  (byte 26832, 16B ok)
#define S_MIDO_OFF  (S_MIDE_OFF + 37*MSTR2*2)   // 6708+5476 = 12184 (16B ok)
#define SMEM_FLOATS (S_MIDO_OFF + 37*MSTR2*2)   // 17660 -> 70640 B

typedef unsigned long long u64;

__constant__ __align__(16) float c_fu[144];
__constant__ __align__(16) float c_fd[144];

__device__ __forceinline__ u64 ffma2(u64 a, u64 b, u64 c) {
    u64 d;
    asm("fma.rn.f32x2 %0, %1, %2, %3;" : "=l"(d) : "l"(a), "l"(b), "l"(c));
    return d;
}
__device__ __forceinline__ float2 unpack2(u64 d) {
    float2 f;
    asm("mov.b64 {%0, %1}, %2;" : "=f"(f.x), "=f"(f.y) : "l"(d));
    return f;
}

// Phase C worker, two output columns per thread.
// hb/ob pre-offset by r0*MSTR2 + 2*lane. acc[2r] = even col, acc[2r+1] = odd.
// Per-output accumulation order identical to the single-col scheme.
template <int NR, int NM>
__device__ __forceinline__ void phase_c2(const u64* __restrict__ hb,
                                         const u64* __restrict__ ob,
                                         u64* __restrict__ acc)
{
    #pragma unroll
    for (int r = 0; r < 2 * NR; r++) acc[r] = 0ull;

    #pragma unroll
    for (int mm = 0; mm < NM; mm++) {
        const u64* mrow = ((mm & 1) ? ob : hb) + (mm >> 1) * MSTR2;
        // pairs 2*lane .. 2*lane+7 via 4x LDS.128 (16B aligned, contiguous)
        const ulonglong2* m2 = (const ulonglong2*)mrow;
        u64 pr[8];
        {
            ulonglong2 a0 = m2[0], a1 = m2[1], a2 = m2[2], a3 = m2[3];
            pr[0] = a0.x; pr[1] = a0.y; pr[2] = a1.x; pr[3] = a1.y;
            pr[4] = a2.x; pr[5] = a2.y; pr[6] = a3.x; pr[7] = a3.y;
        }

        const int rlo = (mm >= 12) ? ((mm - 10) >> 1) : 0;
        const int rhi = (mm >> 1) < (NR - 1) ? (mm >> 1) : (NR - 1);
        #pragma unroll
        for (int r = 0; r < NR; r++) {
            if (r < rlo || r > rhi) continue;       // folds at compile time
            const int ky = mm - 2 * r;              // compile-time constant
            const ulonglong2* fq = (const ulonglong2*)(c_fd + ky * 12);
            ulonglong2 f01 = fq[0], f23 = fq[1], f45 = fq[2];
            acc[2*r]   = ffma2(pr[0], f01.x, acc[2*r]);
            acc[2*r]   = ffma2(pr[1], f01.y, acc[2*r]);
            acc[2*r]   = ffma2(pr[2], f23.x, acc[2*r]);
            acc[2*r]   = ffma2(pr[3], f23.y, acc[2*r]);
            acc[2*r]   = ffma2(pr[4], f45.x, acc[2*r]);
            acc[2*r]   = ffma2(pr[5], f45.y, acc[2*r]);
            acc[2*r+1] = ffma2(pr[1], f01.x, acc[2*r+1]);
            acc[2*r+1] = ffma2(pr[2], f01.y, acc[2*r+1]);
            acc[2*r+1] = ffma2(pr[3], f23.x, acc[2*r+1]);
            acc[2*r+1] = ffma2(pr[4], f23.y, acc[2*r+1]);
            acc[2*r+1] = ffma2(pr[5], f45.x, acc[2*r+1]);
            acc[2*r+1] = ffma2(pr[6], f45.y, acc[2*r+1]);
        }
    }
}

__global__ __launch_bounds__(NTHREADS, 2)
void afa_fused_kernel(const float* __restrict__ in,
                      const float* __restrict__ bias,
                      float* __restrict__ out)
{
    extern __shared__ float sm[];
    float* s_sa   = sm + S_SA_OFF;
    float* s_sb   = sm + S_SB_OFF;
    u64*   s_midE = (u64*)(sm + S_MIDE_OFF);   // even mid rows, (E,O) pairs
    u64*   s_midO = (u64*)(sm + S_MIDO_OFF);   // odd  mid rows

    const int tid   = threadIdx.x;
    const int b     = blockIdx.x;
    const int plane = b >> 3;
    const int t8    = b & 7;
    const int oy0   = (t8 >> 1) * TY;
    const int ox0   = (t8 & 1) * TX;
    const int iy0   = oy0 - 5;
    const int ix0   = ox0 - 5;

    const float bv = __ldg(&bias[plane & 127]);
    const float* __restrict__ inp = in + (size_t)plane * (H * W);

    // ---- Phase A: dual input copies (+bias, zero pad OOB) ------------------
    for (int i = tid; i < INH * INW; i += NTHREADS) {
        const int r  = i / INW;
        const int cc = i - r * INW;
        const int gy = iy0 + r;
        const int gx = ix0 + cc;
        float v = 0.0f;
        if ((unsigned)gy < (unsigned)H && (unsigned)gx < (unsigned)W)
            v = __ldg(&inp[gy * W + gx]) + bv;
        s_sa[i] = v;                       // sA[w] = x[w]
        if (cc > 0) s_sb[i - 1] = v;       // sB[w] = x[w+1]
    }
    __syncthreads();

    // ---- Phase B: row-PAIR polyphase up-conv + activation ------------------
    // Job tid<333: mid rows (2q, 2q+1), 16 columns (8 E/O pairs).
    // Shared input rows q..q+6 loaded once; even row uses fu row 2t (t<6),
    // odd row uses fu row 2t-1 (t>=1). Filter offsets are compile-time.
    // Gain 4 folded into activation gain G.
    const float G = 5.65685424949238019f;   // 4*sqrt(2)
    if (tid < 333) {
        const int chunk = tid / 37;           // 0..8
        const int q     = tid - chunk * 37;   // 0..36
        const int j0    = chunk * 8;          // pair/word column base (even)

        u64 ae[8], ao[8];
        #pragma unroll
        for (int jj = 0; jj < 8; jj++) { ae[jj] = 0ull; ao[jj] = 0ull; }

        #pragma unroll
        for (int t = 0; t < 7; t++) {
            const int rowoff = (q + t) * INW + j0;         // even offset
            const u64* pa = (const u64*)(s_sa + rowoff);   // (x[a],x[a+1]), a even
            const u64* pb = (const u64*)(s_sb + rowoff);   // (x[a],x[a+1]), a odd
            u64 pe[7], po[6];
            #pragma unroll
            for (int m = 0; m < 7; m++) pe[m] = pa[m];
            #pragma unroll
            for (int m = 0; m < 6; m++) po[m] = pb[m];

            #define PR(a) (((a) & 1) ? po[(a) >> 1] : pe[(a) >> 1])
            if (t < 6) {   // even mid row, filter row 2t (compile-time)
                const ulonglong2* fq = (const ulonglong2*)(c_fu + (2 * t) * 12);
                ulonglong2 f01 = fq[0], f23 = fq[1], f45 = fq[2];
                #pragma unroll
                for (int jj = 0; jj < 8; jj++) {
                    ae[jj] = ffma2(PR(jj + 0), f01.x, ae[jj]);
                    ae[jj] = ffma2(PR(jj + 1), f01.y, ae[jj]);
                    ae[jj] = ffma2(PR(jj + 2), f23.x, ae[jj]);
                    ae[jj] = ffma2(PR(jj + 3), f23.y, ae[jj]);
                    ae[jj] = ffma2(PR(jj + 4), f45.x, ae[jj]);
                    ae[jj] = ffma2(PR(jj + 5), f45.y, ae[jj]);
                }
            }
            if (t >= 1) {  // odd mid row, filter row 2t-1 (compile-time)
                const ulonglong2* fq = (const ulonglong2*)(c_fu + (2 * t - 1) * 12);
                ulonglong2 f01 = fq[0], f23 = fq[1], f45 = fq[2];
                #pragma unroll
                for (int jj = 0; jj < 8; jj++) {
                    ao[jj] = ffma2(PR(jj + 0), f01.x, ao[jj]);
                    ao[jj] = ffma2(PR(jj + 1), f01.y, ao[jj]);
                    ao[jj] = ffma2(PR(jj + 2), f23.x, ao[jj]);
                    ao[jj] = ffma2(PR(jj + 3), f23.y, ao[jj]);
                    ao[jj] = ffma2(PR(jj + 4), f45.x, ao[jj]);
                    ao[jj] = ffma2(PR(jj + 5), f45.y, ao[jj]);
                }
            }
            #undef PR
        }
        // activation (gain folded) + STS.128 stores (quad stride 37, clean)
        float4* re = (float4*)(s_midE + q * MSTR2 + j0);
        float4* ro = (float4*)(s_midO + q * MSTR2 + j0);
        #pragma unroll
        for (int k = 0; k < 4; k++) {
            float2 v0 = unpack2(ae[2 * k]);
            float2 v1 = unpack2(ae[2 * k + 1]);
            float4 ve;
            ve.x = fminf(fmaxf(fmaxf(v0.x, 0.2f * v0.x) * G, -256.0f), 256.0f);
            ve.y = fminf(fmaxf(fmaxf(v0.y, 0.2f * v0.y) * G, -256.0f), 256.0f);
            ve.z = fminf(fmaxf(fmaxf(v1.x, 0.2f * v1.x) * G, -256.0f), 256.0f);
            ve.w = fminf(fmaxf(fmaxf(v1.y, 0.2f * v1.y) * G, -256.0f), 256.0f);
            re[k] = ve;
            float2 w0 = unpack2(ao[2 * k]);
            float2 w1 = unpack2(ao[2 * k + 1]);
            float4 vo;
            vo.x = fminf(fmaxf(fmaxf(w0.x, 0.2f * w0.x) * G, -256.0f), 256.0f);
            vo.y = fminf(fmaxf(fmaxf(w0.y, 0.2f * w0.y) * G, -256.0f), 256.0f);
            vo.z = fminf(fmaxf(fmaxf(w1.x, 0.2f * w1.x) * G, -256.0f), 256.0f);
            vo.w = fminf(fmaxf(fmaxf(w1.y, 0.2f * w1.y) * G, -256.0f), 256.0f);
            ro[k] = vo;
        }
    }
    __syncthreads();

    // ---- Phase C: 12x12 down-conv stride 2, two columns per thread ---------
    // 12 warps: warps 0..7 -> 3 rows (r0=3w), warps 8..11 -> 2 rows
    // (r0=24+2(w-8)). Each warp spans all 64 columns (thread = cols 2L,2L+1).
    {
        const int wrp  = tid >> 5;
        const int lane = tid & 31;
        const int c0   = 2 * lane;                  // tile column base
        const int gx0  = ox0 + c0;
        float* op = out + (size_t)plane * (OHW * OHW) + gx0;

        if (wrp < 8) {
            const int r0 = 3 * wrp;
            const u64* hb = s_midE + r0 * MSTR2 + c0;
            const u64* ob = s_midO + r0 * MSTR2 + c0;
            u64 acc[6];
            phase_c2<3, 16>(hb, ob, acc);
            #pragma unroll
            for (int r = 0; r < 3; r++) {
                const int gy = oy0 + r0 + r;
                if (gy < OHW) {
                    float2 v0 = unpack2(acc[2 * r]);
                    float2 v1 = unpack2(acc[2 * r + 1]);
                    if (gx0 < OHW)     op[gy * OHW]     = v0.x + v0.y;
                    if (gx0 + 1 < OHW) op[gy * OHW + 1] = v1.x + v1.y;
                }
            }
        } else {
            const int r0 = 24 + 2 * (wrp - 8);
            const u64* hb = s_midE + r0 * MSTR2 + c0;
            const u64* ob = s_midO + r0 * MSTR2 + c0;
            u64 acc[4];
            phase_c2<2, 14>(hb, ob, acc);
            #pragma unroll
            for (int r = 0; r < 2; r++) {
                const int gy = oy0 + r0 + r;
                if (gy < OHW) {
                    float2 v0 = unpack2(acc[2 * r]);
                    float2 v1 = unpack2(acc[2 * r + 1]);
                    if (gx0 < OHW)     op[gy * OHW]     = v0.x + v0.y;
                    if (gx0 + 1 < OHW) op[gy * OHW + 1] = v1.x + v1.y;
                }
            }
        }
    }
}

extern "C" void kernel_launch(void* const* d_in, const int* in_sizes, int n_in,
                              void* d_out, int out_size)
{
    const float* in   = (const float*)d_in[0];
    const float* bias = (const float*)d_in[1];
    const float* fu   = (const float*)d_in[2];
    const float* fd   = (const float*)d_in[3];
    float* out        = (float*)d_out;

    // Filters into constant memory (async D2D copies: graph-capturable).
    cudaMemcpyToSymbolAsync(c_fu, fu, 144 * sizeof(float), 0,
                            cudaMemcpyDeviceToDevice, 0);
    cudaMemcpyToSymbolAsync(c_fd, fd, 144 * sizeof(float), 0,
                            cudaMemcpyDeviceToDevice, 0);

    const size_t smem = SMEM_FLOATS * sizeof(float);   // 70640 B
    cudaFuncSetAttribute(afa_fused_kernel,
                         cudaFuncAttributeMaxDynamicSharedMemorySize, (int)smem);

    const int nblocks = 1024 * 8;
    afa_fused_kernel<<<nblocks, NTHREADS, smem>>>(in, bias, out);
}

// round 17
// speedup vs baseline: 1.6587x; 1.2688x over previous
#include <cuda_runtime.h>
#include <cuda_bf16.h>

// ---------------------------------------------------------------------------
// AliasFreeActivation: bias -> up2x(12x12 FIR, pad10, gain4) -> lrelu*sqrt2,
// clamp(+-256) -> 12x12 FIR down2x.
// Input [8,128,128,128] f32 -> mid [264,264] -> out [8,128,127,127] f32.
//
// Block = TWO 32x64 output tiles (the two x-halves of one 32-row band),
// software-pipelined: the second tile's global loads are issued before the
// first tile's phase C, burying DRAM latency under FMAs. 384 threads,
// 2 CTAs/SM. Filters in __constant__. Input stored twice (sA, sB=shift-1).
// Phase B: (even,odd) mid-row PAIR per job; STS.128 mid stores (MSTR2=74).
// Phase C: thread = 2 adjacent output columns, 4 LDS.128 per mid row.
// All FMAs are packed fma.rn.f32x2.
// ---------------------------------------------------------------------------

#define H      128
#define W      128
#define OHW    127
#define TY     32
#define TX     64
#define MSTR2  74          // half-mid row stride in u64 pairs (even -> 16B rows)
#define INH    43
#define INW    78          // even => 8B-aligned u64 rows; u64 stride 39%16==7
#define NTHREADS 384
#define NIN    (INH*INW)   // 3354
#define NSTEP  9           // ceil(3354/384)

#define S_SA_OFF    0
#define S_SB_OFF    (INH*INW)                   // 3354
#define S_MIDE_OFF  (2*INH*INW)                 // 6708  (byte 26832, 16B ok)
#define S_MIDO_OFF  (S_MIDE_OFF + 37*MSTR2*2)   // 6708+5476 = 12184 (16B ok)
#define SMEM_FLOATS (S_MIDO_OFF + 37*MSTR2*2)   // 17660 -> 70640 B

typedef unsigned long long u64;

__constant__ __align__(16) float c_fu[144];
__constant__ __align__(16) float c_fd[144];

__device__ __forceinline__ u64 ffma2(u64 a, u64 b, u64 c) {
    u64 d;
    asm("fma.rn.f32x2 %0, %1, %2, %3;" : "=l"(d) : "l"(a), "l"(b), "l"(c));
    return d;
}
__device__ __forceinline__ float2 unpack2(u64 d) {
    float2 f;
    asm("mov.b64 {%0, %1}, %2;" : "=f"(f.x), "=f"(f.y) : "l"(d));
    return f;
}

// One phase-A element: value for linear index i (zero-padded, +bias).
__device__ __forceinline__ float in_val(const float* __restrict__ inp,
                                        float bv, int iy0, int ix0, int i)
{
    const int r  = i / INW;
    const int cc = i - r * INW;
    const int gy = iy0 + r;
    const int gx = ix0 + cc;
    float v = 0.0f;
    if ((unsigned)gy < (unsigned)H && (unsigned)gx < (unsigned)W)
        v = __ldg(&inp[gy * W + gx]) + bv;
    return v;
}

// Phase C worker, two output columns per thread (identical to R15).
template <int NR, int NM>
__device__ __forceinline__ void phase_c2(const u64* __restrict__ hb,
                                         const u64* __restrict__ ob,
                                         u64* __restrict__ acc)
{
    #pragma unroll
    for (int r = 0; r < 2 * NR; r++) acc[r] = 0ull;

    #pragma unroll
    for (int mm = 0; mm < NM; mm++) {
        const u64* mrow = ((mm & 1) ? ob : hb) + (mm >> 1) * MSTR2;
        const ulonglong2* m2 = (const ulonglong2*)mrow;
        u64 pr[8];
        {
            ulonglong2 a0 = m2[0], a1 = m2[1], a2 = m2[2], a3 = m2[3];
            pr[0] = a0.x; pr[1] = a0.y; pr[2] = a1.x; pr[3] = a1.y;
            pr[4] = a2.x; pr[5] = a2.y; pr[6] = a3.x; pr[7] = a3.y;
        }

        const int rlo = (mm >= 12) ? ((mm - 10) >> 1) : 0;
        const int rhi = (mm >> 1) < (NR - 1) ? (mm >> 1) : (NR - 1);
        #pragma unroll
        for (int r = 0; r < NR; r++) {
            if (r < rlo || r > rhi) continue;       // folds at compile time
            const int ky = mm - 2 * r;              // compile-time constant
            const ulonglong2* fq = (const ulonglong2*)(c_fd + ky * 12);
            ulonglong2 f01 = fq[0], f23 = fq[1], f45 = fq[2];
            acc[2*r]   = ffma2(pr[0], f01.x, acc[2*r]);
            acc[2*r]   = ffma2(pr[1], f01.y, acc[2*r]);
            acc[2*r]   = ffma2(pr[2], f23.x, acc[2*r]);
            acc[2*r]   = ffma2(pr[3], f23.y, acc[2*r]);
            acc[2*r]   = ffma2(pr[4], f45.x, acc[2*r]);
            acc[2*r]   = ffma2(pr[5], f45.y, acc[2*r]);
            acc[2*r+1] = ffma2(pr[1], f01.x, acc[2*r+1]);
            acc[2*r+1] = ffma2(pr[2], f01.y, acc[2*r+1]);
            acc[2*r+1] = ffma2(pr[3], f23.x, acc[2*r+1]);
            acc[2*r+1] = ffma2(pr[4], f23.y, acc[2*r+1]);
            acc[2*r+1] = ffma2(pr[5], f45.x, acc[2*r+1]);
            acc[2*r+1] = ffma2(pr[6], f45.y, acc[2*r+1]);
        }
    }
}

__global__ __launch_bounds__(NTHREADS, 2)
void afa_fused_kernel(const float* __restrict__ in,
                      const float* __restrict__ bias,
                      float* __restrict__ out)
{
    extern __shared__ float sm[];
    float* s_sa   = sm + S_SA_OFF;
    float* s_sb   = sm + S_SB_OFF;
    u64*   s_midE = (u64*)(sm + S_MIDE_OFF);   // even mid rows, (E,O) pairs
    u64*   s_midO = (u64*)(sm + S_MIDO_OFF);   // odd  mid rows

    const int tid   = threadIdx.x;
    const int b     = blockIdx.x;
    const int plane = b >> 2;                  // n*128 + c
    const int oy0   = (b & 3) * TY;            // shared by both tiles
    const int iy0   = oy0 - 5;

    const float bv = __ldg(&bias[plane & 127]);
    const float* __restrict__ inp = in + (size_t)plane * (H * W);
    const float G = 5.65685424949238019f;      // 4*sqrt(2), up-gain folded

    // ---- Prologue: phase A for tile k=0 (ix0 = -5) -------------------------
    #pragma unroll
    for (int s = 0; s < NSTEP; s++) {
        const int i = tid + s * NTHREADS;
        if (i < NIN) {
            const float v = in_val(inp, bv, iy0, -5, i);
            s_sa[i] = v;
            const int cc = i - (i / INW) * INW;
            if (cc > 0) s_sb[i - 1] = v;
        }
    }
    __syncthreads();

    #pragma unroll
    for (int k = 0; k < 2; k++) {
        const int ox0 = k * TX;

        // ---- Phase B: row-PAIR polyphase up-conv + activation --------------
        if (tid < 333) {
            const int chunk = tid / 37;           // 0..8
            const int q     = tid - chunk * 37;   // 0..36
            const int j0    = chunk * 8;          // pair/word column base

            u64 ae[8], ao[8];
            #pragma unroll
            for (int jj = 0; jj < 8; jj++) { ae[jj] = 0ull; ao[jj] = 0ull; }

            #pragma unroll
            for (int t = 0; t < 7; t++) {
                const int rowoff = (q + t) * INW + j0;
                const u64* pa = (const u64*)(s_sa + rowoff);
                const u64* pb = (const u64*)(s_sb + rowoff);
                u64 pe[7], po[6];
                #pragma unroll
                for (int m = 0; m < 7; m++) pe[m] = pa[m];
                #pragma unroll
                for (int m = 0; m < 6; m++) po[m] = pb[m];

                #define PR(a) (((a) & 1) ? po[(a) >> 1] : pe[(a) >> 1])
                if (t < 6) {   // even mid row, filter row 2t
                    const ulonglong2* fq = (const ulonglong2*)(c_fu + (2 * t) * 12);
                    ulonglong2 f01 = fq[0], f23 = fq[1], f45 = fq[2];
                    #pragma unroll
                    for (int jj = 0; jj < 8; jj++) {
                        ae[jj] = ffma2(PR(jj + 0), f01.x, ae[jj]);
                        ae[jj] = ffma2(PR(jj + 1), f01.y, ae[jj]);
                        ae[jj] = ffma2(PR(jj + 2), f23.x, ae[jj]);
                        ae[jj] = ffma2(PR(jj + 3), f23.y, ae[jj]);
                        ae[jj] = ffma2(PR(jj + 4), f45.x, ae[jj]);
                        ae[jj] = ffma2(PR(jj + 5), f45.y, ae[jj]);
                    }
                }
                if (t >= 1) {  // odd mid row, filter row 2t-1
                    const ulonglong2* fq = (const ulonglong2*)(c_fu + (2 * t - 1) * 12);
                    ulonglong2 f01 = fq[0], f23 = fq[1], f45 = fq[2];
                    #pragma unroll
                    for (int jj = 0; jj < 8; jj++) {
                        ao[jj] = ffma2(PR(jj + 0), f01.x, ao[jj]);
                        ao[jj] = ffma2(PR(jj + 1), f01.y, ao[jj]);
                        ao[jj] = ffma2(PR(jj + 2), f23.x, ao[jj]);
                        ao[jj] = ffma2(PR(jj + 3), f23.y, ao[jj]);
                        ao[jj] = ffma2(PR(jj + 4), f45.x, ao[jj]);
                        ao[jj] = ffma2(PR(jj + 5), f45.y, ao[jj]);
                    }
                }
                #undef PR
            }
            // activation + STS.128 stores (quad stride 37, conflict-free)
            float4* re = (float4*)(s_midE + q * MSTR2 + j0);
            float4* ro = (float4*)(s_midO + q * MSTR2 + j0);
            #pragma unroll
            for (int kk = 0; kk < 4; kk++) {
                float2 v0 = unpack2(ae[2 * kk]);
                float2 v1 = unpack2(ae[2 * kk + 1]);
                float4 ve;
                ve.x = fminf(fmaxf(fmaxf(v0.x, 0.2f * v0.x) * G, -256.0f), 256.0f);
                ve.y = fminf(fmaxf(fmaxf(v0.y, 0.2f * v0.y) * G, -256.0f), 256.0f);
                ve.z = fminf(fmaxf(fmaxf(v1.x, 0.2f * v1.x) * G, -256.0f), 256.0f);
                ve.w = fminf(fmaxf(fmaxf(v1.y, 0.2f * v1.y) * G, -256.0f), 256.0f);
                re[kk] = ve;
                float2 w0 = unpack2(ao[2 * kk]);
                float2 w1 = unpack2(ao[2 * kk + 1]);
                float4 vo;
                vo.x = fminf(fmaxf(fmaxf(w0.x, 0.2f * w0.x) * G, -256.0f), 256.0f);
                vo.y = fminf(fmaxf(fmaxf(w0.y, 0.2f * w0.y) * G, -256.0f), 256.0f);
                vo.z = fminf(fmaxf(fmaxf(w1.x, 0.2f * w1.x) * G, -256.0f), 256.0f);
                vo.w = fminf(fmaxf(fmaxf(w1.y, 0.2f * w1.y) * G, -256.0f), 256.0f);
                ro[kk] = vo;
            }
        }
        __syncthreads();

        // ---- Pipelined phase A for tile 1: issue LDGs BEFORE phase C -------
        float va[NSTEP];
        if (k == 0) {
            #pragma unroll
            for (int s = 0; s < NSTEP; s++) {
                const int i = tid + s * NTHREADS;
                va[s] = (i < NIN) ? in_val(inp, bv, iy0, TX - 5, i) : 0.0f;
            }
        }

        // ---- Phase C: 12x12 down-conv stride 2, two columns per thread -----
        {
            const int wrp  = tid >> 5;
            const int lane = tid & 31;
            const int c0   = 2 * lane;
            const int gx0  = ox0 + c0;
            float* op = out + (size_t)plane * (OHW * OHW) + gx0;

            if (wrp < 8) {
                const int r0 = 3 * wrp;
                const u64* hb = s_midE + r0 * MSTR2 + c0;
                const u64* ob = s_midO + r0 * MSTR2 + c0;
                u64 acc[6];
                phase_c2<3, 16>(hb, ob, acc);
                #pragma unroll
                for (int r = 0; r < 3; r++) {
                    const int gy = oy0 + r0 + r;
                    if (gy < OHW) {
                        float2 v0 = unpack2(acc[2 * r]);
                        float2 v1 = unpack2(acc[2 * r + 1]);
                        if (gx0 < OHW)     op[gy * OHW]     = v0.x + v0.y;
                        if (gx0 + 1 < OHW) op[gy * OHW + 1] = v1.x + v1.y;
                    }
                }
            } else {
                const int r0 = 24 + 2 * (wrp - 8);
                const u64* hb = s_midE + r0 * MSTR2 + c0;
                const u64* ob = s_midO + r0 * MSTR2 + c0;
                u64 acc[4];
                phase_c2<2, 14>(hb, ob, acc);
                #pragma unroll
                for (int r = 0; r < 2; r++) {
                    const int gy = oy0 + r0 + r;
                    if (gy < OHW) {
                        float2 v0 = unpack2(acc[2 * r]);
                        float2 v1 = unpack2(acc[2 * r + 1]);
                        if (gx0 < OHW)     op[gy * OHW]     = v0.x + v0.y;
                        if (gx0 + 1 < OHW) op[gy * OHW + 1] = v1.x + v1.y;
                    }
                }
            }
        }

        // ---- Commit pipelined phase A, then barrier before B(1) ------------
        if (k == 0) {
            #pragma unroll
            for (int s = 0; s < NSTEP; s++) {
                const int i = tid + s * NTHREADS;
                if (i < NIN) {
                    s_sa[i] = va[s];
                    const int cc = i - (i / INW) * INW;
                    if (cc > 0) s_sb[i - 1] = va[s];
                }
            }
            __syncthreads();
        }
    }
}

extern "C" void kernel_launch(void* const* d_in, const int* in_sizes, int n_in,
                              void* d_out, int out_size)
{
    const float* in   = (const float*)d_in[0];
    const float* bias = (const float*)d_in[1];
    const float* fu   = (const float*)d_in[2];
    const float* fd   = (const float*)d_in[3];
    float* out        = (float*)d_out;

    // Filters into constant memory (async D2D copies: graph-capturable).
    cudaMemcpyToSymbolAsync(c_fu, fu, 144 * sizeof(float), 0,
                            cudaMemcpyDeviceToDevice, 0);
    cudaMemcpyToSymbolAsync(c_fd, fd, 144 * sizeof(float), 0,
                            cudaMemcpyDeviceToDevice, 0);

    const size_t smem = SMEM_FLOATS * sizeof(float);   // 70640 B
    cudaFuncSetAttribute(afa_fused_kernel,
                         cudaFuncAttributeMaxDynamicSharedMemorySize, (int)smem);

    const int nblocks = 1024 * 4;   // planes * 4 y-bands; 2 x-tiles per block
    afa_fused_kernel<<<nblocks, NTHREADS, smem>>>(in, bias, out);
}